// round 9
// baseline (speedup 1.0000x reference)
#include <cuda_runtime.h>

#define BATCH 512
#define SLEN  1024
#define TAGS  64
#define WARPS_PER_CTA 4
#define CHAINS_PER_WARP 2
#define THREADS (32 * WARPS_PER_CTA)
#define GRID (BATCH / (WARPS_PER_CTA * CHAINS_PER_WARP))   // 64

// ---------------------------------------------------------------------------
// Packed f32x2 + ordered smem helpers (sm_103a)
// ---------------------------------------------------------------------------
__device__ __forceinline__ unsigned long long ffma2(unsigned long long a,
                                                    unsigned long long b,
                                                    unsigned long long c) {
    unsigned long long d;
    asm("fma.rn.f32x2 %0, %1, %2, %3;" : "=l"(d) : "l"(a), "l"(b), "l"(c));
    return d;
}
__device__ __forceinline__ unsigned long long fadd2(unsigned long long a,
                                                    unsigned long long b) {
    unsigned long long d;
    asm("add.rn.f32x2 %0, %1, %2;" : "=l"(d) : "l"(a), "l"(b));
    return d;
}
__device__ __forceinline__ float2 unpack2(unsigned long long v) {
    float2 f;
    asm("mov.b64 {%0, %1}, %2;" : "=f"(f.x), "=f"(f.y) : "l"(v));
    return f;
}
__device__ __forceinline__ unsigned long long pack2(float lo, float hi) {
    unsigned long long v;
    asm("mov.b64 %0, {%1, %2};" : "=l"(v) : "f"(lo), "f"(hi));
    return v;
}
__device__ __forceinline__ void sts64(unsigned addr, unsigned long long v) {
    asm volatile("st.shared.b64 [%0], %1;" :: "r"(addr), "l"(v) : "memory");
}
__device__ __forceinline__ ulonglong2 lds128(unsigned addr) {
    ulonglong2 r;
    asm volatile("ld.shared.v2.b64 {%0, %1}, [%2];"
                 : "=l"(r.x), "=l"(r.y) : "r"(addr) : "memory");
    return r;
}

// ---------------------------------------------------------------------------
// TWO independent chains per WARP, interleaved stepA;stepB to fill each
// other's latency bubbles. Both chains share the register-resident
// E = exp(transitions) (lane owns rows j0=2*lane, j1=2*lane+1, packed f32x2).
// Alpha exchange per chain: one STS.64 -> 16 broadcast LDS.128; a full
// other-chain step sits between a chain's STS and its next LDS, so smem
// visibility latency is fully shadowed. No barriers / syncwarp at all.
//
// Linear-domain recurrence a'[j] = exp(emit[j]) * sum_i a[i]*E[j,i];
// inputs 0,1 are identically zero (NO_TRANS rows) and are skipped.
// Renorm every 8th step (odd t only -> even-position steps branch-free)
// by scalar proxy a[3] (= lane1.r1, always > 0); RCP/LG2 off-path on MUFU.
// exp(emit) computed one step ahead; emissions (LDG.64) prefetched 4 ahead.
// ---------------------------------------------------------------------------
__global__ void __launch_bounds__(THREADS, 1)
crf_dual_kernel(const float* __restrict__ feats,
                const int*   __restrict__ tags,
                const int*   __restrict__ lengths,
                const float* __restrict__ trans,
                const int*   __restrict__ start_p,
                const int*   __restrict__ stop_p,
                float*       __restrict__ out) {
    const int warp = threadIdx.x >> 5;
    const int lane = threadIdx.x & 31;
    const int gw   = blockIdx.x * WARPS_PER_CTA + warp;
    const int bA   = gw * 2;
    const int bB   = gw * 2 + 1;
    const int j0   = 2 * lane;
    const int j1   = 2 * lane + 1;

    __shared__ __align__(16) float a_s[WARPS_PER_CTA][CHAINS_PER_WARP][2][TAGS];

    const int lenA  = lengths[bA];
    const int lenB  = lengths[bB];
    const int start = *start_p;
    const int stop  = *stop_p;

    // Shared (between chains) packed rows of E = exp(trans):
    // Eq0[k] = (E[j0,2k], E[j0,2k+1]), Eq1[k] = (E[j1,2k], E[j1,2k+1])
    unsigned long long Eq0[TAGS / 2], Eq1[TAGS / 2];
    {
        const float2* t0 = (const float2*)(trans + j0 * TAGS);
        const float2* t1 = (const float2*)(trans + j1 * TAGS);
#pragma unroll
        for (int k = 0; k < 32; k++) {
            float2 v = t0[k];
            Eq0[k] = pack2(__expf(v.x), __expf(v.y));
            float2 w = t1[k];
            Eq1[k] = pack2(__expf(w.x), __expf(w.y));
        }
    }

    const float* fbA = feats + (size_t)bA * SLEN * TAGS + j0;
    const float* fbB = feats + (size_t)bB * SLEN * TAGS + j0;

    const unsigned bufA0 = (unsigned)__cvta_generic_to_shared(&a_s[warp][0][0][0]);
    const unsigned bufA1 = (unsigned)__cvta_generic_to_shared(&a_s[warp][0][1][0]);
    const unsigned bufB0 = (unsigned)__cvta_generic_to_shared(&a_s[warp][1][0][0]);
    const unsigned bufB1 = (unsigned)__cvta_generic_to_shared(&a_s[warp][1][1][0]);

    // ---- step 0 closed form: a1[j] = exp(trans[j,start]) * exp(emit0[j]) ----
    // (states 0,1 get exp(-10000) == 0 exactly -> inputs 0,1 dead forever)
    float etj0 = __expf(trans[j0 * TAGS + start]);
    float etj1 = __expf(trans[j1 * TAGS + start]);
    float2 e0A = *(const float2*)fbA;
    float2 e0B = *(const float2*)fbB;
    float rA0 = etj0 * __expf(e0A.x), rA1 = etj1 * __expf(e0A.y);
    float rB0 = etj0 * __expf(e0B.x), rB1 = etj1 * __expf(e0B.y);
    sts64(bufA0 + 8u * lane, pack2(rA0, rA1));
    sts64(bufB0 + 8u * lane, pack2(rB0, rB1));
    float C2A = 0.0f, C2B = 0.0f;

    // Emission prefetch rings (depth 4) per chain: q1X/q2X/q3X = e[t+1..t+3],
    // exX0/exX1 = exp(e_t). Names chosen so macro pasting is q1##SFX etc.
    float2 evA = *(const float2*)(fbA + TAGS);
    float2 evB = *(const float2*)(fbB + TAGS);
    float exA0 = __expf(evA.x), exA1 = __expf(evA.y);
    float exB0 = __expf(evB.x), exB1 = __expf(evB.y);
    float2 q1A = *(const float2*)(fbA + 2 * TAGS);
    float2 q2A = *(const float2*)(fbA + 3 * TAGS);
    float2 q3A = *(const float2*)(fbA + 4 * TAGS);
    float2 q1B = *(const float2*)(fbB + 2 * TAGS);
    float2 q2B = *(const float2*)(fbB + 3 * TAGS);
    float2 q3B = *(const float2*)(fbB + 4 * TAGS);

    const int lenM = (lenA > lenB) ? lenA : lenB;

// One forward step for chain SFX. RENORM: compile-time flag (renorm steps have
// t odd, so only odd-position expansions check). Inner FFMA loop skips the
// dead inputs 0,1 (k=0 keeps only the (a2,a3) half).
#define CRF_STEP(T, SFX, SRC, DST, RENORM)                                     \
    if ((T) < len##SFX) {                                                      \
        float sc0 = ex##SFX##0, sc1 = ex##SFX##1;                              \
        if ((RENORM) && (((T) & 7) == 7)) {                                    \
            float a3  = __shfl_sync(0xFFFFFFFFu, r##SFX##1, 1);                \
            float inv = __fdividef(1.0f, a3);                                  \
            sc0 *= inv; sc1 *= inv;                                            \
            C2##SFX += __log2f(a3);                                            \
        }                                                                      \
        ex##SFX##0 = __expf(q1##SFX.x);                                        \
        ex##SFX##1 = __expf(q1##SFX.y);                                        \
        q1##SFX = q2##SFX; q2##SFX = q3##SFX;                                  \
        int tp_ = (T) + 4; if (tp_ > SLEN - 1) tp_ = SLEN - 1;                 \
        q3##SFX = *(const float2*)(fb##SFX + (size_t)tp_ * TAGS);              \
        unsigned long long c00, c01, c10, c11;                                 \
        {                                                                      \
            ulonglong2 ap0 = lds128(SRC);                                      \
            c01 = ffma2(ap0.y, Eq0[1], 0ull);   /* inputs 2,3 */               \
            c11 = ffma2(ap0.y, Eq1[1], 0ull);                                  \
            c00 = 0ull; c10 = 0ull;             /* inputs 0,1 dead */          \
        }                                                                      \
        _Pragma("unroll")                                                      \
        for (int k = 1; k < 16; k++) {                                         \
            ulonglong2 ap = lds128((SRC) + 16u * k);                           \
            c00 = ffma2(ap.x, Eq0[2 * k],     c00);                            \
            c10 = ffma2(ap.x, Eq1[2 * k],     c10);                            \
            c01 = ffma2(ap.y, Eq0[2 * k + 1], c01);                            \
            c11 = ffma2(ap.y, Eq1[2 * k + 1], c11);                            \
        }                                                                      \
        float2 f0 = unpack2(fadd2(c00, c01));                                  \
        float2 f1 = unpack2(fadd2(c10, c11));                                  \
        r##SFX##0 = (f0.x + f0.y) * sc0;                                       \
        r##SFX##1 = (f1.x + f1.y) * sc1;                                       \
        sts64((DST) + 8u * lane, pack2(r##SFX##0, r##SFX##1));                 \
    }

    int t = 1;
#pragma unroll 1
    while (t + 1 < lenM) {
        // odd position (renorm possible)
        CRF_STEP(t,     A, bufA0, bufA1, 1)
        CRF_STEP(t,     B, bufB0, bufB1, 1)
        // even position (branch-free)
        CRF_STEP(t + 1, A, bufA1, bufA0, 0)
        CRF_STEP(t + 1, B, bufB1, bufB0, 0)
        t += 2;
    }
    if (t < lenM) {
        CRF_STEP(t, A, bufA0, bufA1, 1)
        CRF_STEP(t, B, bufB0, bufB1, 1)
    }
#undef CRF_STEP

    // ---- finalize both chains: gold score + alpha -> out ----
    float es0 = __expf(trans[stop * TAGS + j0]);
    float es1 = __expf(trans[stop * TAGS + j1]);

#pragma unroll
    for (int c = 0; c < 2; c++) {
        const int   b   = (c == 0) ? bA : bB;
        const int   len = (c == 0) ? lenA : lenB;
        const float r0  = (c == 0) ? rA0 : rB0;
        const float r1  = (c == 0) ? rA1 : rB1;
        const float C2  = (c == 0) ? C2A : C2B;

        const int*   tg    = tags  + (size_t)b * SLEN;
        const float* fbase = feats + (size_t)b * SLEN * TAGS;
        float g = 0.0f;
        for (int tt = lane; tt < len; tt += 32) {
            int tn = tg[tt];
            int tc = (tt == 0) ? start : tg[tt - 1];
            g += trans[tn * TAGS + tc] + fbase[(size_t)tt * TAGS + tn];
        }
        float v = r0 * es0 + r1 * es1;
#pragma unroll
        for (int off = 16; off > 0; off >>= 1) {
            v += __shfl_xor_sync(0xFFFFFFFFu, v, off);
            g += __shfl_xor_sync(0xFFFFFFFFu, g, off);
        }
        if (lane == 0) {
            int end = tg[len - 1];
            float alpha = C2 * 0.6931471805599453f + __logf(v);
            out[b] = alpha - (g + trans[stop * TAGS + end]);
        }
    }
}

// ---------------------------------------------------------------------------
// Inputs (metadata order):
//   0 feats [B,S,T] f32, 1 tags [B,S] i32, 2 lengths [B] i32,
//   3 masks [B,S] f32 (== t<len, unused), 4 transitions [T,T] f32,
//   5 start_idx i32, 6 stop_idx i32
// ---------------------------------------------------------------------------
extern "C" void kernel_launch(void* const* d_in, const int* in_sizes, int n_in,
                              void* d_out, int out_size) {
    const float* feats   = (const float*)d_in[0];
    const int*   tags    = (const int*)d_in[1];
    const int*   lengths = (const int*)d_in[2];
    const float* trans   = (const float*)d_in[4];
    const int*   start_p = (const int*)d_in[5];
    const int*   stop_p  = (const int*)d_in[6];
    float* out = (float*)d_out;

    crf_dual_kernel<<<GRID, THREADS>>>(feats, tags, lengths, trans,
                                       start_p, stop_p, out);
}

// round 10
// speedup vs baseline: 2.4084x; 2.4084x over previous
#include <cuda_runtime.h>

#define BATCH 512
#define SLEN  1024
#define TAGS  64
#define CHAINS 4                 // chains per CTA
#define THREADS (CHAINS * 2 * 32)  // 4 main + 4 producer warps
#define GRID (BATCH / CHAINS)    // 128
#define RING 32                  // ring entries (power of 2)

// ---------------------------------------------------------------------------
// Packed f32x2 + smem helpers (sm_103a)
// ---------------------------------------------------------------------------
__device__ __forceinline__ unsigned long long ffma2(unsigned long long a,
                                                    unsigned long long b,
                                                    unsigned long long c) {
    unsigned long long d;
    asm("fma.rn.f32x2 %0, %1, %2, %3;" : "=l"(d) : "l"(a), "l"(b), "l"(c));
    return d;
}
__device__ __forceinline__ unsigned long long fadd2(unsigned long long a,
                                                    unsigned long long b) {
    unsigned long long d;
    asm("add.rn.f32x2 %0, %1, %2;" : "=l"(d) : "l"(a), "l"(b));
    return d;
}
__device__ __forceinline__ float2 unpack2(unsigned long long v) {
    float2 f;
    asm("mov.b64 {%0, %1}, %2;" : "=f"(f.x), "=f"(f.y) : "l"(v));
    return f;
}
__device__ __forceinline__ unsigned long long pack2(float lo, float hi) {
    unsigned long long v;
    asm("mov.b64 %0, {%1, %2};" : "=l"(v) : "f"(lo), "f"(hi));
    return v;
}
__device__ __forceinline__ void sts64(unsigned addr, unsigned long long v) {
    asm volatile("st.shared.b64 [%0], %1;" :: "r"(addr), "l"(v) : "memory");
}
__device__ __forceinline__ void sts64f(unsigned addr, float2 v) {
    asm volatile("st.shared.v2.f32 [%0], {%1, %2};"
                 :: "r"(addr), "f"(v.x), "f"(v.y) : "memory");
}
__device__ __forceinline__ ulonglong2 lds128(unsigned addr) {
    ulonglong2 r;
    asm volatile("ld.shared.v2.b64 {%0, %1}, [%2];"
                 : "=l"(r.x), "=l"(r.y) : "r"(addr) : "memory");
    return r;
}
__device__ __forceinline__ float2 lds64f(unsigned addr) {
    float2 r;
    asm volatile("ld.shared.v2.f32 {%0, %1}, [%2];"
                 : "=f"(r.x), "=f"(r.y) : "r"(addr) : "memory");
    return r;
}
__device__ __forceinline__ unsigned ldacq(unsigned addr) {
    unsigned v;
    asm volatile("ld.acquire.cta.shared.u32 %0, [%1];"
                 : "=r"(v) : "r"(addr) : "memory");
    return v;
}
__device__ __forceinline__ void strel(unsigned addr, unsigned v) {
    asm volatile("st.release.cta.shared.u32 [%0], %1;"
                 :: "r"(addr), "r"(v) : "memory");
}

// ---------------------------------------------------------------------------
// Warp-specialized CRF forward:
//  - main warp w (0..3): the sequential linear-domain recurrence for batch
//    b = blockIdx*4 + w. Step = LDS.64 ring scale + 16 LDS.128 + 62 FFMA2 +
//    tail + STS.64. Nothing else: no LDG, no exp, no index math.
//  - producer warp w+4: streams exp(feats[b,t,:]) into a 32-entry smem ring,
//    8 entries per publish, st.release/ld.acquire flow control.
// Renorm every 8th step (static position in the 8-unrolled block) by scalar
// proxy a[3] (= lane1.r1, always > 0). Inputs 0,1 dead (NO_TRANS) -> skipped.
// ---------------------------------------------------------------------------
__global__ void __launch_bounds__(THREADS, 1)
crf_pipe_kernel(const float* __restrict__ feats,
                const int*   __restrict__ tags,
                const int*   __restrict__ lengths,
                const float* __restrict__ trans,
                const int*   __restrict__ start_p,
                const int*   __restrict__ stop_p,
                float*       __restrict__ out) {
    const int wid  = threadIdx.x >> 5;
    const int lane = threadIdx.x & 31;
    const bool is_main = (wid < CHAINS);
    const int cw = is_main ? wid : wid - CHAINS;
    const int b  = blockIdx.x * CHAINS + cw;

    __shared__ __align__(16) float a_s[CHAINS][2][TAGS];
    __shared__ __align__(16) float ring[CHAINS][RING][TAGS];
    __shared__ unsigned pcount[CHAINS];   // last entry produced
    __shared__ unsigned mcount[CHAINS];   // last entry consumed

    if (threadIdx.x < CHAINS) { pcount[threadIdx.x] = 0; mcount[threadIdx.x] = 0; }
    __syncthreads();

    const int len   = lengths[b];
    const int start = *start_p;
    const int stop  = *stop_p;

    const unsigned pc_addr   = (unsigned)__cvta_generic_to_shared(&pcount[cw]);
    const unsigned mc_addr   = (unsigned)__cvta_generic_to_shared(&mcount[cw]);
    const unsigned ring_base = (unsigned)__cvta_generic_to_shared(&ring[cw][0][0]);

    // ======================= PRODUCER WARP =======================
    if (!is_main) {
        const float* fp = feats + (size_t)b * SLEN * TAGS + 2 * lane;
        unsigned my_m = 0;
        int e = 1;
        while (e < len) {
            int emax = e + 7; if (emax > len - 1) emax = len - 1;
            // backpressure: never run more than RING-8 entries ahead
            while ((int)(emax - my_m) > RING - 8) my_m = ldacq(mc_addr);
            const int n = emax - e + 1;
            float2 v[8];
#pragma unroll
            for (int i = 0; i < 8; i++)
                if (i < n) v[i] = *(const float2*)(fp + (size_t)(e + i) * TAGS);
#pragma unroll
            for (int i = 0; i < 8; i++)
                if (i < n) {
                    float2 w;
                    w.x = __expf(v[i].x);
                    w.y = __expf(v[i].y);
                    unsigned slot = (unsigned)(e + i) & (RING - 1);
                    sts64f(ring_base + (slot << 8) + ((unsigned)lane << 3), w);
                }
            strel(pc_addr, (unsigned)emax);   // publish (orders ring writes)
            e = emax + 1;
        }
        return;
    }

    // ========================= MAIN WARP =========================
    const int j0 = 2 * lane;
    const int j1 = 2 * lane + 1;

    // Packed rows of E = exp(trans): Eq0[k]=(E[j0,2k],E[j0,2k+1]), Eq1 same for j1.
    unsigned long long Eq0[TAGS / 2], Eq1[TAGS / 2];
    {
        const float2* t0 = (const float2*)(trans + j0 * TAGS);
        const float2* t1 = (const float2*)(trans + j1 * TAGS);
#pragma unroll
        for (int k = 0; k < 32; k++) {
            float2 v = t0[k];
            Eq0[k] = pack2(__expf(v.x), __expf(v.y));
            float2 w = t1[k];
            Eq1[k] = pack2(__expf(w.x), __expf(w.y));
        }
    }

    const unsigned buf0 = (unsigned)__cvta_generic_to_shared(&a_s[cw][0][0]);
    const unsigned buf1 = (unsigned)__cvta_generic_to_shared(&a_s[cw][1][0]);

    // ---- step 0 closed form: a1[j] = exp(trans[j,start]) * exp(emit0[j]) ----
    const float* fb = feats + (size_t)b * SLEN * TAGS + j0;
    float2 e0 = *(const float2*)fb;
    float r0 = __expf(trans[j0 * TAGS + start]) * __expf(e0.x);
    float r1 = __expf(trans[j1 * TAGS + start]) * __expf(e0.y);
    sts64(buf0 + 8u * lane, pack2(r0, r1));
    float C2 = 0.0f;

    unsigned seen = 0;  // cached producer progress
#define WAITP(need) while ((int)seen < (need)) seen = ldacq(pc_addr)

// One forward step. Scale pair comes from the ring (already exp'd).
// Inner FFMA loop skips dead inputs 0,1 (k=0 keeps only the (a2,a3) half).
#define STEP(T, SRC, DST, RENORM)                                              \
    {                                                                          \
        float2 sc = lds64f(ring_base + ((((unsigned)(T)) & (RING - 1)) << 8)   \
                           + ((unsigned)lane << 3));                           \
        float sc0 = sc.x, sc1 = sc.y;                                          \
        if (RENORM) {                                                          \
            float a3  = __shfl_sync(0xFFFFFFFFu, r1, 1);                       \
            float inv = __fdividef(1.0f, a3);                                  \
            sc0 *= inv; sc1 *= inv;                                            \
            C2 += __log2f(a3);                                                 \
        }                                                                      \
        unsigned long long c00, c01, c10, c11;                                 \
        {                                                                      \
            ulonglong2 ap0 = lds128(SRC);                                      \
            c01 = ffma2(ap0.y, Eq0[1], 0ull);                                  \
            c11 = ffma2(ap0.y, Eq1[1], 0ull);                                  \
            c00 = 0ull; c10 = 0ull;                                            \
        }                                                                      \
        _Pragma("unroll")                                                      \
        for (int k = 1; k < 16; k++) {                                         \
            ulonglong2 ap = lds128((SRC) + 16u * k);                           \
            c00 = ffma2(ap.x, Eq0[2 * k],     c00);                            \
            c10 = ffma2(ap.x, Eq1[2 * k],     c10);                            \
            c01 = ffma2(ap.y, Eq0[2 * k + 1], c01);                            \
            c11 = ffma2(ap.y, Eq1[2 * k + 1], c11);                            \
        }                                                                      \
        float2 f0 = unpack2(fadd2(c00, c01));                                  \
        float2 f1 = unpack2(fadd2(c10, c11));                                  \
        r0 = (f0.x + f0.y) * sc0;                                              \
        r1 = (f1.x + f1.y) * sc1;                                              \
        sts64((DST) + 8u * lane, pack2(r0, r1));                               \
    }

    int t = 1;
#pragma unroll 1
    while (t + 7 < len) {
        WAITP(t + 7);
        STEP(t,     buf0, buf1, 0)
        STEP(t + 1, buf1, buf0, 0)
        STEP(t + 2, buf0, buf1, 0)
        STEP(t + 3, buf1, buf0, 0)
        STEP(t + 4, buf0, buf1, 0)
        STEP(t + 5, buf1, buf0, 0)
        STEP(t + 6, buf0, buf1, 1)   // t+6 = 8k+7 -> renorm (static)
        STEP(t + 7, buf1, buf0, 0)
        strel(mc_addr, (unsigned)(t + 7));
        t += 8;
    }
#pragma unroll 1
    while (t < len) {
        WAITP(t);
        if (t & 1) {
            STEP(t, buf0, buf1, ((t & 7) == 7))
        } else {
            STEP(t, buf1, buf0, ((t & 7) == 7))
        }
        t++;
    }
#undef STEP
#undef WAITP

    // ---- gold path score: 32-way strided gather-sum ----
    const int*   tg    = tags  + (size_t)b * SLEN;
    const float* fbase = feats + (size_t)b * SLEN * TAGS;
    float g = 0.0f;
    for (int tt = lane; tt < len; tt += 32) {
        int tn = tg[tt];
        int tc = (tt == 0) ? start : tg[tt - 1];
        g += trans[tn * TAGS + tc] + fbase[(size_t)tt * TAGS + tn];
    }

    // ---- alpha = C + log( sum_j a_final[j] * exp(trans[stop, j]) ) ----
    float v = r0 * __expf(trans[stop * TAGS + j0]) +
              r1 * __expf(trans[stop * TAGS + j1]);
#pragma unroll
    for (int off = 16; off > 0; off >>= 1) {
        v += __shfl_xor_sync(0xFFFFFFFFu, v, off);
        g += __shfl_xor_sync(0xFFFFFFFFu, g, off);
    }

    if (lane == 0) {
        int end = tg[len - 1];
        float alpha = C2 * 0.6931471805599453f + __logf(v);
        out[b] = alpha - (g + trans[stop * TAGS + end]);
    }
}

// ---------------------------------------------------------------------------
// Inputs (metadata order):
//   0 feats [B,S,T] f32, 1 tags [B,S] i32, 2 lengths [B] i32,
//   3 masks [B,S] f32 (== t<len, unused), 4 transitions [T,T] f32,
//   5 start_idx i32, 6 stop_idx i32
// ---------------------------------------------------------------------------
extern "C" void kernel_launch(void* const* d_in, const int* in_sizes, int n_in,
                              void* d_out, int out_size) {
    const float* feats   = (const float*)d_in[0];
    const int*   tags    = (const int*)d_in[1];
    const int*   lengths = (const int*)d_in[2];
    const float* trans   = (const float*)d_in[4];
    const int*   start_p = (const int*)d_in[5];
    const int*   stop_p  = (const int*)d_in[6];
    float* out = (float*)d_out;

    crf_pipe_kernel<<<GRID, THREADS>>>(feats, tags, lengths, trans,
                                       start_p, stop_p, out);
}